// round 10
// baseline (speedup 1.0000x reference)
#include <cuda_runtime.h>
#include <cuda_bf16.h>

#define T_DIM 512
#define B_DIM 128
#define E_DIM 256
#define KMAX  512
#define TB    (T_DIM * B_DIM)

typedef unsigned long long ull;

// Scratch (__device__ globals: allocation-free).
__device__ float g_Cp[B_DIM * T_DIM];                 // prefix of (d-u), [b][t]
__device__ float g_M [B_DIM * T_DIM];                 // M_t = d_t - Cp_t, [b][t]
__device__ float g_bc[(size_t)KMAX * TB];             // coeffs, layout [k][t][b]
__device__ int   g_nb[TB];                            // band length, [t][b]

__device__ __forceinline__ ull ffma2(ull a, ull b, ull c) {
  ull d;
  asm("fma.rn.f32x2 %0, %1, %2, %3;" : "=l"(d) : "l"(a), "l"(b), "l"(c));
  return d;
}
__device__ __forceinline__ ull pack_dup(float c) {
  ull r; unsigned int cu = __float_as_uint(c);
  asm("mov.b64 %0, {%1, %1};" : "=l"(r) : "r"(cu));
  return r;
}

// ---------------------------------------------------------------------------
// Kernel 1: per-batch inclusive prefix sum of (d - u); emit Cp and M.
// ---------------------------------------------------------------------------
__global__ __launch_bounds__(T_DIM) void prefix_kernel(
    const float* __restrict__ u, const float* __restrict__ d) {
  const int b = blockIdx.x, tid = threadIdx.x;
  __shared__ float s[T_DIM];
  const float dt = d[tid * B_DIM + b];
  s[tid] = dt - u[tid * B_DIM + b];
  __syncthreads();
  #pragma unroll
  for (int off = 1; off < T_DIM; off <<= 1) {
    float o = (tid >= off) ? s[tid - off] : 0.f;
    __syncthreads();
    s[tid] += o;
    __syncthreads();
  }
  const float Cp = s[tid];
  g_Cp[b * T_DIM + tid] = Cp;
  g_M [b * T_DIM + tid] = dt - Cp;
}

// ---------------------------------------------------------------------------
// Kernel 2: coefficient walk, one thread per (t,b); warp lanes = consecutive
// b at the SAME t, so coefficient stores (layout [k][t][b]) are coalesced.
//   coeff_k = min(Cp_t + runmax_{j=t-k..t} M_j, 1) - prev;  stop at 1.
// Per-lane M walk is backward stride-1 within one b-row: L1-resident.
// ---------------------------------------------------------------------------
__global__ __launch_bounds__(256) void walk_kernel() {
  const int gid = blockIdx.x * 256 + threadIdx.x;
  const int b   = gid & (B_DIM - 1);
  const int t   = gid >> 7;

  const float* __restrict__ Mb = &g_M[b * T_DIM];
  const float Cpt = __ldg(&g_Cp[b * T_DIM + t]);

  float rm = -3.4e38f, prev = 0.f;
  int nb = t + 1;
  int k = 0;
  for (int j = t; j >= 0; --j, ++k) {
    rm = fmaxf(rm, __ldg(&Mb[j]));
    const float pc = fminf(Cpt + rm, 1.f);
    g_bc[(size_t)k * TB + t * B_DIM + b] = pc - prev;   // coalesced over b
    prev = pc;
    if (pc >= 1.f) { nb = k + 1; break; }
  }
  g_nb[t * B_DIM + b] = nb;
}

// ---------------------------------------------------------------------------
// Kernel 3: banded read. Block = 256 threads = 8 warps; warp w owns batch
// b = blockIdx.y*8 + w and walks 8 consecutive t's (t0..t0+7) sequentially.
// Lane covers 8 floats of E (2 x LDG.128). Per t: its own band only — no
// cross-t max coupling. Coefficients are warp-uniform __ldg broadcasts.
// Consecutive t's re-read overlapping v rows -> L1 temporal hits.
// ---------------------------------------------------------------------------
__global__ __launch_bounds__(256) void read_kernel(
    const float* __restrict__ v, float* __restrict__ out) {
  const int warp = threadIdx.x >> 5;
  const int lane = threadIdx.x & 31;
  const int t0   = blockIdx.x * 8;
  const int b    = blockIdx.y * 8 + warp;

  const size_t eoff = (size_t)b * E_DIM + lane * 8;
  const float4* __restrict__ vbase = (const float4*)(v + eoff);
  const size_t row4 = (size_t)B_DIM * E_DIM / 4;        // v row stride, float4

  #pragma unroll 1
  for (int tt = 0; tt < 8; ++tt) {
    const int t  = t0 + tt;
    const int nb = __ldg(&g_nb[t * B_DIM + b]);
    const float* __restrict__ crow = &g_bc[t * B_DIM + b];

    ull a0 = 0ull, a1 = 0ull, a2 = 0ull, a3 = 0ull;
    for (int k = 0; k < nb; ++k) {
      const ull cc = pack_dup(__ldg(crow + (size_t)k * TB));  // uniform
      const size_t roff = (size_t)(t - k) * row4;
      const float4 f0 = vbase[roff];
      const float4 f1 = vbase[roff + 1];
      a0 = ffma2(cc, *(const ull*)&f0.x, a0);
      a1 = ffma2(cc, *(const ull*)&f0.z, a1);
      a2 = ffma2(cc, *(const ull*)&f1.x, a2);
      a3 = ffma2(cc, *(const ull*)&f1.z, a3);
    }

    float4* o = (float4*)(out + (size_t)t * B_DIM * E_DIM + eoff);
    float4 r0, r1;
    *(ull*)&r0.x = a0; *(ull*)&r0.z = a1;
    *(ull*)&r1.x = a2; *(ull*)&r1.z = a3;
    o[0] = r0;
    o[1] = r1;
  }
}

// ---------------------------------------------------------------------------
// Inputs: v [T,B,E] f32, u [T,B] f32, d [T,B] f32. Output: reads [T,B,E] f32.
// ---------------------------------------------------------------------------
extern "C" void kernel_launch(void* const* d_in, const int* in_sizes, int n_in,
                              void* d_out, int out_size) {
  const float* v = (const float*)d_in[0];
  const float* u = (const float*)d_in[1];
  const float* d = (const float*)d_in[2];
  float* out = (float*)d_out;

  prefix_kernel<<<B_DIM, T_DIM>>>(u, d);
  walk_kernel<<<TB / 256, 256>>>();

  dim3 grid(T_DIM / 8, B_DIM / 8);
  read_kernel<<<grid, 256>>>(v, out);
}

// round 13
// speedup vs baseline: 5.6713x; 5.6713x over previous
#include <cuda_runtime.h>
#include <cuda_bf16.h>

#define T_DIM 512
#define B_DIM 128
#define E_DIM 256
#define KMAX  512

// Scratch (__device__ globals: allocation-free).
__device__ float g_Cp[B_DIM * T_DIM];                 // prefix of (d-u), [b][t]
__device__ float g_M [B_DIM * T_DIM];                 // M_t = d_t - Cp_t, [b][t]
__device__ float g_bc[(size_t)T_DIM * B_DIM * KMAX];  // coeffs [t][b][k], k contig
__device__ int   g_nb[T_DIM * B_DIM];                 // band length [t][b]

// ---------------------------------------------------------------------------
// Kernel 1: per-batch inclusive prefix sum of (d - u); emit Cp and M.
// ---------------------------------------------------------------------------
__global__ __launch_bounds__(T_DIM) void prefix_kernel(
    const float* __restrict__ u, const float* __restrict__ d) {
  const int b = blockIdx.x, tid = threadIdx.x;
  __shared__ float s[T_DIM];
  const float dt = d[tid * B_DIM + b];
  s[tid] = dt - u[tid * B_DIM + b];
  __syncthreads();
  #pragma unroll
  for (int off = 1; off < T_DIM; off <<= 1) {
    float o = (tid >= off) ? s[tid - off] : 0.f;
    __syncthreads();
    s[tid] += o;
    __syncthreads();
  }
  const float Cp = s[tid];
  g_Cp[b * T_DIM + tid] = Cp;
  g_M [b * T_DIM + tid] = dt - Cp;
}

// ---------------------------------------------------------------------------
// Kernel 2: coefficient walk. One thread per (t,b); warp lanes = consecutive
// t at the SAME b, so all lanes walk the same 2KB M row (L1-resident,
// coalesced backward reads).
//   coeff_k = min(Cp_t + runmax_{j=t-k..t} M_j, 1) - prev;  stop at pc >= 1
// (running max monotone => all deeper coeffs exactly 0).
// Writes compact rows g_bc[t][b][0..nb) — k contiguous for the read kernel.
// ---------------------------------------------------------------------------
__global__ __launch_bounds__(256) void walk_kernel() {
  const int gid = blockIdx.x * 256 + threadIdx.x;
  const int t   = gid & (T_DIM - 1);
  const int b   = gid >> 9;

  const float* __restrict__ Mb = &g_M[b * T_DIM];
  const float Cpt = __ldg(&g_Cp[b * T_DIM + t]);
  float* __restrict__ row = &g_bc[((size_t)t * B_DIM + b) * KMAX];

  float rm = -3.4e38f, prev = 0.f;
  int nb = t + 1;
  int k = 0;
  for (int j = t; j >= 0; --j, ++k) {
    rm = fmaxf(rm, __ldg(&Mb[j]));
    const float pc = fminf(Cpt + rm, 1.f);
    row[k] = pc - prev;
    prev = pc;
    if (pc >= 1.f) { nb = k + 1; break; }
  }
  g_nb[t * B_DIM + b] = nb;
}

// ---------------------------------------------------------------------------
// Kernel 3: banded read (round-3 proven form). One block per (t,b),
// 64 threads x float4 over E. Coefficient loads are warp-uniform broadcasts
// from the contiguous band row. Loads are unconditional so consecutive k
// iterations pipeline (no data-dependent branch between LDGs).
// ---------------------------------------------------------------------------
__global__ __launch_bounds__(64) void read_kernel(
    const float* __restrict__ v, float* __restrict__ out) {
  const int t  = blockIdx.x;
  const int b  = blockIdx.y;
  const int e4 = threadIdx.x;                 // 64 threads * 4 floats = 256

  const int nb = g_nb[t * B_DIM + b];
  const float* __restrict__ bcrow = &g_bc[((size_t)t * B_DIM + b) * KMAX];

  const float4* __restrict__ vb =
      (const float4*)(v + (size_t)b * E_DIM) + e4;
  const size_t row4 = (size_t)B_DIM * E_DIM / 4;

  float4 acc = make_float4(0.f, 0.f, 0.f, 0.f);
  #pragma unroll 2
  for (int k = 0; k < nb; ++k) {
    const float c = __ldg(&bcrow[k]);
    const float4 vv = vb[(size_t)(t - k) * row4];
    acc.x = fmaf(c, vv.x, acc.x);
    acc.y = fmaf(c, vv.y, acc.y);
    acc.z = fmaf(c, vv.z, acc.z);
    acc.w = fmaf(c, vv.w, acc.w);
  }
  ((float4*)out)[((size_t)t * B_DIM + b) * (E_DIM / 4) + e4] = acc;
}

// ---------------------------------------------------------------------------
// Inputs: v [T,B,E] f32, u [T,B] f32, d [T,B] f32. Output: reads [T,B,E] f32.
// ---------------------------------------------------------------------------
extern "C" void kernel_launch(void* const* d_in, const int* in_sizes, int n_in,
                              void* d_out, int out_size) {
  const float* v = (const float*)d_in[0];
  const float* u = (const float*)d_in[1];
  const float* d = (const float*)d_in[2];
  float* out = (float*)d_out;

  prefix_kernel<<<B_DIM, T_DIM>>>(u, d);
  walk_kernel<<<(T_DIM * B_DIM) / 256, 256>>>();

  dim3 grid(T_DIM, B_DIM);
  read_kernel<<<grid, 64>>>(v, out);
}